// round 8
// baseline (speedup 1.0000x reference)
#include <cuda_runtime.h>
#include <math.h>
#include <stddef.h>

#define B 32
#define H 512
#define V 32000
#define T 64
#define VB 128
#define NB 250            /* V / VB */
#define START_INDEX 1
#define XPAD 516          /* float pad: conflict-free 16B smem reads */

typedef unsigned long long u64;

/* ------------------------- persistent device scratch ---------------------- */
__device__ float g_h0[2][B * H];
__device__ float g_c0[B * H];
__device__ float g_h1[2][B * H];
__device__ float g_c1[B * H];
__device__ float g_pre0[2048 * B];    /* ctx part of layer0 gates + b_ih + b_hh */
__device__ float g_pmax[NB * B];
__device__ float g_psum[NB * B];
__device__ int   g_pidx[NB * B];
__device__ float g_lse[T * B];

__device__ __forceinline__ float sigf(float x) { return 1.0f / (1.0f + expf(-x)); }

/* packed fp32x2 FMA: d.lo += a.lo*b.lo ; d.hi += a.hi*b.hi */
__device__ __forceinline__ void fma2(u64& d, u64 a, u64 b) {
    asm("fma.rn.f32x2 %0, %1, %2, %0;" : "+l"(d) : "l"(a), "l"(b));
}
union F2U { u64 u; float2 f; };
__device__ __forceinline__ float f2sum(u64 v) { F2U t; t.u = v; return t.f.x + t.f.y; }

/* ---------------------------------------------------------------------------
 * k_pre: blocks [0,256): pre0[r][b] = W_ih_l0[r][512:] . ctx[b] + b_ih + b_hh
 *        blocks [256,264): zero all states.
 * ------------------------------------------------------------------------- */
__global__ __launch_bounds__(256) void k_pre(const float* __restrict__ ctx,
                                             const float* __restrict__ Wih0,
                                             const float* __restrict__ bih0,
                                             const float* __restrict__ bhh0) {
    int blk = blockIdx.x, tid = threadIdx.x;
    if (blk >= 256) {
        int g = (blk - 256) * 256 + tid;
        for (int i = g; i < B * H; i += 2048) {
            g_h0[0][i] = 0.0f; g_h0[1][i] = 0.0f; g_c0[i] = 0.0f;
            g_h1[0][i] = 0.0f; g_h1[1][i] = 0.0f; g_c1[i] = 0.0f;
        }
        return;
    }
    extern __shared__ float smem[];
    float* s_x = smem;                            /* [32][XPAD] */
    for (int i = tid; i < B * 512; i += 256) {
        int b = i >> 9, k = i & 511;
        s_x[b * XPAD + k] = ctx[i];
    }
    __syncthreads();
    int w = tid >> 5, lane = tid & 31;
    int r = blk * 8 + w;
    const ulonglong2* wp = (const ulonglong2*)(Wih0 + (size_t)r * 1024 + 512);
    const ulonglong2* xp = (const ulonglong2*)(s_x + lane * XPAD);
    u64 acc = 0;
#pragma unroll 4
    for (int q = 0; q < 128; q++) {
        ulonglong2 a = wp[q], x = xp[q];
        fma2(acc, a.x, x.x);
        fma2(acc, a.y, x.y);
    }
    g_pre0[r * 32 + lane] = f2sum(acc) + bih0[r] + bhh0[r];
}

/* ---------------------------------------------------------------------------
 * k_lstm0: 128 blocks x 512 thr. Prologue: argmax (all blocks, no expf in
 * chain); block 0 also computes lse[t-1]. Then layer-0 LSTM, 4 hidden units
 * per block. Warp w: gate rq = w>>2, k-quarter kq = w&3, 4 rows.
 * ------------------------------------------------------------------------- */
__global__ __launch_bounds__(512) void k_lstm0(int t,
                                               const float* __restrict__ emb,
                                               const float* __restrict__ Wih0,
                                               const float* __restrict__ Whh0) {
    extern __shared__ float smem[];
    float* s_xa = smem;                     /* [32][XPAD] emb(tok)   */
    float* s_xb = s_xa + 32 * XPAD;         /* [32][XPAD] h0 prev    */
    float* s_p  = s_xb + 32 * XPAD;         /* [4][16][32]           */
    float* s_rm = s_p + 4 * 16 * 32;        /* [16][32]              */
    int*   s_ri = (int*)(s_rm + 16 * 32);   /* [16][32]              */
    float* s_rs = (float*)(s_ri + 16 * 32); /* [16][32]              */
    int*   s_tok = (int*)(s_rs + 16 * 32);  /* [32]                  */
    float* s_fm  = (float*)(s_tok + 32);    /* [32]                  */

    int tid = threadIdx.x, blk = blockIdx.x;
    int prev = t & 1, nxt = prev ^ 1;

    /* --- pass 1: max + first-index argmax (no expf in the chain) --- */
    if (t > 0) {
        int b = tid & 31, g = tid >> 5;     /* g in 0..15 */
        float m = -3.0e38f; int mi = 0x7fffffff;
        for (int p = g; p < NB; p += 16) {
            float pm = g_pmax[p * 32 + b];
            int   pi = g_pidx[p * 32 + b];
            if (pm > m || (pm == m && pi < mi)) { m = pm; mi = pi; }
        }
        s_rm[g * 32 + b] = m; s_ri[g * 32 + b] = mi;
    }
    __syncthreads();
    if (tid < 32) {
        if (t > 0) {
            float m = s_rm[tid]; int mi = s_ri[tid];
            for (int g = 1; g < 16; g++) {
                float pm = s_rm[g * 32 + tid];
                int   pi = s_ri[g * 32 + tid];
                if (pm > m || (pm == m && pi < mi)) { m = pm; mi = pi; }
            }
            s_tok[tid] = mi; s_fm[tid] = m;
        } else {
            s_tok[tid] = START_INDEX;
        }
    }
    __syncthreads();

    /* --- pass 2 (block 0 only): lse[t-1]; independent expfs --- */
    if (t > 0 && blk == 0) {
        int b = tid & 31, g = tid >> 5;
        float mb = s_fm[b];
        float s = 0.0f;
        for (int p = g; p < NB; p += 16)
            s += g_psum[p * 32 + b] * expf(g_pmax[p * 32 + b] - mb);
        s_rs[g * 32 + b] = s;
        __syncthreads();
        if (tid < 32) {
            float s2 = 0.0f;
            for (int g2 = 0; g2 < 16; g2++) s2 += s_rs[g2 * 32 + tid];
            g_lse[(t - 1) * 32 + tid] = s_fm[tid] + logf(s2);
        }
    }

    /* --- load both x operands --- */
    for (int i = tid; i < 32 * 128; i += 512) {
        int b = i >> 7, q = i & 127;
        *(float4*)(s_xa + b * XPAD + 4 * q) =
            *(const float4*)(emb + (size_t)s_tok[b] * 512 + 4 * q);
        *(float4*)(s_xb + b * XPAD + 4 * q) =
            *(const float4*)(&g_h0[prev][b * 512 + 4 * q]);
    }
    __syncthreads();

    int w = tid >> 5, lane = tid & 31;
    int rq = w >> 2, kq = w & 3;
    int j0 = blk * 4;
    u64 acc[4] = {0, 0, 0, 0};

    /* phase A: W_ih_l0[:, :512] @ emb(tok)  (row stride 1024 fl = 256 u2) */
    {
        const ulonglong2* xp = (const ulonglong2*)(s_xa + lane * XPAD);
        const ulonglong2* wp = (const ulonglong2*)(Wih0 + (size_t)(rq * 512 + j0) * 1024);
#pragma unroll 8
        for (int q = kq * 32; q < kq * 32 + 32; q++) {
            ulonglong2 xv = xp[q];
            ulonglong2 w0 = wp[q], w1 = wp[256 + q], w2 = wp[512 + q], w3 = wp[768 + q];
            fma2(acc[0], w0.x, xv.x); fma2(acc[0], w0.y, xv.y);
            fma2(acc[1], w1.x, xv.x); fma2(acc[1], w1.y, xv.y);
            fma2(acc[2], w2.x, xv.x); fma2(acc[2], w2.y, xv.y);
            fma2(acc[3], w3.x, xv.x); fma2(acc[3], w3.y, xv.y);
        }
    }
    /* phase B: W_hh_l0 @ h0_prev  (row stride 512 fl = 128 u2) */
    {
        const ulonglong2* xp = (const ulonglong2*)(s_xb + lane * XPAD);
        const ulonglong2* wp = (const ulonglong2*)(Whh0 + (size_t)(rq * 512 + j0) * 512);
#pragma unroll 8
        for (int q = kq * 32; q < kq * 32 + 32; q++) {
            ulonglong2 xv = xp[q];
            ulonglong2 w0 = wp[q], w1 = wp[128 + q], w2 = wp[256 + q], w3 = wp[384 + q];
            fma2(acc[0], w0.x, xv.x); fma2(acc[0], w0.y, xv.y);
            fma2(acc[1], w1.x, xv.x); fma2(acc[1], w1.y, xv.y);
            fma2(acc[2], w2.x, xv.x); fma2(acc[2], w2.y, xv.y);
            fma2(acc[3], w3.x, xv.x); fma2(acc[3], w3.y, xv.y);
        }
    }
#pragma unroll
    for (int j = 0; j < 4; j++)
        s_p[(kq * 16 + rq * 4 + j) * 32 + lane] = f2sum(acc[j]);
    __syncthreads();

    if (tid < 128) {
        int jl = tid >> 5, b = tid & 31;
        int jg = j0 + jl;
        float gsum[4];
#pragma unroll
        for (int g = 0; g < 4; g++) {
            float s = 0.0f;
#pragma unroll
            for (int k = 0; k < 4; k++) s += s_p[(k * 16 + g * 4 + jl) * 32 + b];
            gsum[g] = s + g_pre0[(g * 512 + jg) * 32 + b];
        }
        float c  = g_c0[b * 512 + jg];
        float cn = sigf(gsum[1]) * c + sigf(gsum[0]) * tanhf(gsum[2]);
        float hn = sigf(gsum[3]) * tanhf(cn);
        g_c0[b * 512 + jg] = cn;
        g_h0[nxt][b * 512 + jg] = hn;
    }
}

/* ---------------------------------------------------------------------------
 * k_lstm1: 128 blocks x 512 thr. x = h0[nxt], h = h1[prev].
 * ------------------------------------------------------------------------- */
__global__ __launch_bounds__(512) void k_lstm1(int t,
                                               const float* __restrict__ Wih1,
                                               const float* __restrict__ Whh1,
                                               const float* __restrict__ bih1,
                                               const float* __restrict__ bhh1) {
    extern __shared__ float smem[];
    float* s_xa = smem;                     /* [32][XPAD] h0 new  */
    float* s_xb = s_xa + 32 * XPAD;         /* [32][XPAD] h1 prev */
    float* s_p  = s_xb + 32 * XPAD;         /* [4][16][32]        */
    int tid = threadIdx.x, blk = blockIdx.x;
    int prev = t & 1, nxt = prev ^ 1;

    for (int i = tid; i < 32 * 128; i += 512) {
        int b = i >> 7, q = i & 127;
        *(float4*)(s_xa + b * XPAD + 4 * q) =
            *(const float4*)(&g_h0[nxt][b * 512 + 4 * q]);
        *(float4*)(s_xb + b * XPAD + 4 * q) =
            *(const float4*)(&g_h1[prev][b * 512 + 4 * q]);
    }
    __syncthreads();

    int w = tid >> 5, lane = tid & 31;
    int rq = w >> 2, kq = w & 3;
    int j0 = blk * 4;
    u64 acc[4] = {0, 0, 0, 0};

    {
        const ulonglong2* xp = (const ulonglong2*)(s_xa + lane * XPAD);
        const ulonglong2* wp = (const ulonglong2*)(Wih1 + (size_t)(rq * 512 + j0) * 512);
#pragma unroll 8
        for (int q = kq * 32; q < kq * 32 + 32; q++) {
            ulonglong2 xv = xp[q];
            ulonglong2 w0 = wp[q], w1 = wp[128 + q], w2 = wp[256 + q], w3 = wp[384 + q];
            fma2(acc[0], w0.x, xv.x); fma2(acc[0], w0.y, xv.y);
            fma2(acc[1], w1.x, xv.x); fma2(acc[1], w1.y, xv.y);
            fma2(acc[2], w2.x, xv.x); fma2(acc[2], w2.y, xv.y);
            fma2(acc[3], w3.x, xv.x); fma2(acc[3], w3.y, xv.y);
        }
    }
    {
        const ulonglong2* xp = (const ulonglong2*)(s_xb + lane * XPAD);
        const ulonglong2* wp = (const ulonglong2*)(Whh1 + (size_t)(rq * 512 + j0) * 512);
#pragma unroll 8
        for (int q = kq * 32; q < kq * 32 + 32; q++) {
            ulonglong2 xv = xp[q];
            ulonglong2 w0 = wp[q], w1 = wp[128 + q], w2 = wp[256 + q], w3 = wp[384 + q];
            fma2(acc[0], w0.x, xv.x); fma2(acc[0], w0.y, xv.y);
            fma2(acc[1], w1.x, xv.x); fma2(acc[1], w1.y, xv.y);
            fma2(acc[2], w2.x, xv.x); fma2(acc[2], w2.y, xv.y);
            fma2(acc[3], w3.x, xv.x); fma2(acc[3], w3.y, xv.y);
        }
    }
#pragma unroll
    for (int j = 0; j < 4; j++)
        s_p[(kq * 16 + rq * 4 + j) * 32 + lane] = f2sum(acc[j]);
    __syncthreads();

    if (tid < 128) {
        int jl = tid >> 5, b = tid & 31;
        int jg = j0 + jl;
        float gsum[4];
#pragma unroll
        for (int g = 0; g < 4; g++) {
            float s = 0.0f;
#pragma unroll
            for (int k = 0; k < 4; k++) s += s_p[(k * 16 + g * 4 + jl) * 32 + b];
            int rr = g * 512 + jg;
            gsum[g] = s + bih1[rr] + bhh1[rr];
        }
        float c  = g_c1[b * 512 + jg];
        float cn = sigf(gsum[1]) * c + sigf(gsum[0]) * tanhf(gsum[2]);
        float hn = sigf(gsum[3]) * tanhf(cn);
        g_c1[b * 512 + jg] = cn;
        g_h1[nxt][b * 512 + jg] = hn;
    }
}

/* ---------------------------------------------------------------------------
 * k_logits: 500 blocks (250 v-tiles x 2 batch-halves) x 256 thr.
 * Block = 128 vocab rows x 16 batches; thread tile 4v x 2b.
 * smem halved -> 3 blocks/SM; unroll 4 -> higher MLP.
 * ------------------------------------------------------------------------- */
__global__ __launch_bounds__(256, 3) void k_logits(int t,
                                                   const float* __restrict__ Wout,
                                                   const float* __restrict__ bout,
                                                   float* __restrict__ out) {
    extern __shared__ float smem[];
    float* s_h  = smem;                    /* [16][XPAD] */
    float* s_rm = s_h + 16 * XPAD;         /* [32][16]   */
    float* s_rs = s_rm + 32 * 16;
    int*   s_ri = (int*)(s_rs + 32 * 16);
    int tid = threadIdx.x, blk = blockIdx.x;
    int vt = blk >> 1, bh = blk & 1;
    int vb = vt * VB, b0 = bh * 16;
    int nxt = (t & 1) ^ 1;

    for (int i = tid; i < 16 * 128; i += 256) {
        int b = i >> 7, q = i & 127;
        *(float4*)(s_h + b * XPAD + 4 * q) =
            *(const float4*)(&g_h1[nxt][(b0 + b) * 512 + 4 * q]);
    }
    __syncthreads();

    int vg = tid >> 3, bg = tid & 7;       /* vg 0..31, bg 0..7 */
    u64 acc[4][2];
#pragma unroll
    for (int j = 0; j < 4; j++) { acc[j][0] = 0; acc[j][1] = 0; }

    const ulonglong2* wr = (const ulonglong2*)(Wout + (size_t)(vb + vg) * 512);
#pragma unroll 4
    for (int q = 0; q < 128; q++) {
        ulonglong2 hv0 = *(const ulonglong2*)(s_h + bg * XPAD + 4 * q);
        ulonglong2 hv1 = *(const ulonglong2*)(s_h + (bg + 8) * XPAD + 4 * q);
        ulonglong2 wv[4];
#pragma unroll
        for (int j = 0; j < 4; j++)
            wv[j] = wr[j * 4096 + q];      /* 32 rows * 128 u2/row */
#pragma unroll
        for (int j = 0; j < 4; j++) {
            fma2(acc[j][0], wv[j].x, hv0.x);
            fma2(acc[j][0], wv[j].y, hv0.y);
            fma2(acc[j][1], wv[j].x, hv1.x);
            fma2(acc[j][1], wv[j].y, hv1.y);
        }
    }

    float bj[4];
#pragma unroll
    for (int j = 0; j < 4; j++) bj[j] = bout[vb + vg + 32 * j];

#pragma unroll
    for (int i = 0; i < 2; i++) {
        int bl = bg + 8 * i;               /* local batch 0..15 */
        int b  = b0 + bl;
        float l4[4];
        float m = -3.0e38f; int mi = 0;
#pragma unroll
        for (int j = 0; j < 4; j++) {
            float l = f2sum(acc[j][i]) + bj[j];
            l4[j] = l;
            int v = vb + vg + 32 * j;
            if (l > m) { m = l; mi = v; }  /* ascending v -> first-index ties */
            __stcs(&out[(size_t)b * ((size_t)T * V) + (size_t)t * V + v], l);
        }
        float s = 0.f;
#pragma unroll
        for (int j = 0; j < 4; j++) s += expf(l4[j] - m);
        s_rm[vg * 16 + bl] = m; s_rs[vg * 16 + bl] = s; s_ri[vg * 16 + bl] = mi;
    }
    __syncthreads();

    if (tid < 16) {
        int bl = tid;
        float m = s_rm[bl]; int mi = s_ri[bl];
        for (int g = 1; g < 32; g++) {     /* pass 1: max/idx chain, no expf */
            float pm = s_rm[g * 16 + bl]; int pi = s_ri[g * 16 + bl];
            if (pm > m || (pm == m && pi < mi)) { m = pm; mi = pi; }
        }
        float s = 0.f;                     /* pass 2: independent expfs */
        for (int g = 0; g < 32; g++) s += s_rs[g * 16 + bl] * expf(s_rm[g * 16 + bl] - m);
        g_pmax[vt * 32 + b0 + bl] = m;
        g_psum[vt * 32 + b0 + bl] = s;
        g_pidx[vt * 32 + b0 + bl] = mi;
    }
}

/* final-step LSE */
__global__ void k_finlse() {
    __shared__ float s_rm[8 * 32], s_rs[8 * 32];
    __shared__ float s_fm[32];
    int tid = threadIdx.x;
    int b = tid & 31, g = tid >> 5;
    float m = -3.0e38f;
    for (int p = g; p < NB; p += 8) m = fmaxf(m, g_pmax[p * 32 + b]);
    s_rm[g * 32 + b] = m;
    __syncthreads();
    if (tid < 32) {
        float m2 = s_rm[tid];
        for (int g2 = 1; g2 < 8; g2++) m2 = fmaxf(m2, s_rm[g2 * 32 + tid]);
        s_fm[tid] = m2;
    }
    __syncthreads();
    float mb = s_fm[b];
    float s = 0.0f;
    for (int p = g; p < NB; p += 8)
        s += g_psum[p * 32 + b] * expf(g_pmax[p * 32 + b] - mb);
    s_rs[g * 32 + b] = s;
    __syncthreads();
    if (tid < 32) {
        float s2 = 0.0f;
        for (int g2 = 0; g2 < 8; g2++) s2 += s_rs[g2 * 32 + tid];
        g_lse[(T - 1) * 32 + tid] = s_fm[tid] + logf(s2);
    }
}

/* out[b][t][v] -= lse[t][b]; streaming loads/stores */
__global__ __launch_bounds__(256) void k_norm(float* __restrict__ out) {
    int i4 = blockIdx.x * 256 + threadIdx.x;
    int flat = i4 * 4;
    int b   = flat / (T * V);
    int rem = flat - b * (T * V);
    int tt  = rem / V;
    float l = g_lse[tt * 32 + b];
    float4* p = (float4*)out + i4;
    float4 v = __ldcs(p);
    v.x -= l; v.y -= l; v.z -= l; v.w -= l;
    __stcs(p, v);
}

/* -------------------------------- launch ---------------------------------- */
#define SM_PRE  (32 * XPAD * 4)
#define SM_L0   ((2 * 32 * XPAD + 4 * 16 * 32 + 3 * 16 * 32 + 64) * 4)
#define SM_L1   ((2 * 32 * XPAD + 4 * 16 * 32) * 4)
#define SM_LOG  ((16 * XPAD + 3 * 32 * 16) * 4)

extern "C" void kernel_launch(void* const* d_in, const int* in_sizes, int n_in,
                              void* d_out, int out_size) {
    const float* ctx  = (const float*)d_in[0];
    const float* emb  = (const float*)d_in[1];
    const float* Wih0 = (const float*)d_in[2];
    const float* Whh0 = (const float*)d_in[3];
    const float* bih0 = (const float*)d_in[4];
    const float* bhh0 = (const float*)d_in[5];
    const float* Wih1 = (const float*)d_in[6];
    const float* Whh1 = (const float*)d_in[7];
    const float* bih1 = (const float*)d_in[8];
    const float* bhh1 = (const float*)d_in[9];
    const float* Wout = (const float*)d_in[10];
    const float* bout = (const float*)d_in[11];
    float* out = (float*)d_out;

    cudaFuncSetAttribute(k_pre,    cudaFuncAttributeMaxDynamicSharedMemorySize, SM_PRE);
    cudaFuncSetAttribute(k_lstm0,  cudaFuncAttributeMaxDynamicSharedMemorySize, SM_L0);
    cudaFuncSetAttribute(k_lstm1,  cudaFuncAttributeMaxDynamicSharedMemorySize, SM_L1);
    cudaFuncSetAttribute(k_logits, cudaFuncAttributeMaxDynamicSharedMemorySize, SM_LOG);

    k_pre<<<264, 256, SM_PRE>>>(ctx, Wih0, bih0, bhh0);
    for (int t = 0; t < T; t++) {
        k_lstm0<<<128, 512, SM_L0>>>(t, emb, Wih0, Whh0);
        k_lstm1<<<128, 512, SM_L1>>>(t, Wih1, Whh1, bih1, bhh1);
        k_logits<<<500, 256, SM_LOG>>>(t, Wout, bout, out);
    }
    k_finlse<<<1, 256>>>();
    k_norm<<<64000, 256>>>(out);
}

// round 9
// speedup vs baseline: 1.1423x; 1.1423x over previous
#include <cuda_runtime.h>
#include <math.h>
#include <stddef.h>

#define B 32
#define H 512
#define V 32000
#define T 64
#define GRID 128
#define NT 512
#define NTILE 250           /* 250 logits tiles of 128 vocab rows */
#define START_INDEX 1
#define XPAD 516            /* conflict-free 16B smem reads, lane = batch */

typedef unsigned long long u64;

/* ------------------------- persistent device scratch ---------------------- */
__device__ float g_h0[2][B * H];
__device__ float g_c0[B * H];
__device__ float g_h1[2][B * H];
__device__ float g_c1[B * H];
__device__ float g_pre0[2048 * B];  /* ctx part of layer0 gates + b_ih + b_hh */
__device__ float g_pmax[NTILE * B];
__device__ float g_psum[NTILE * B];
__device__ int   g_pidx[NTILE * B];
__device__ float g_lse[T * B];
__device__ int            g_bar_count;
__device__ volatile int   g_bar_gen;

__device__ __forceinline__ float sigf(float x) { return 1.0f / (1.0f + expf(-x)); }

/* packed fp32x2 FMA: d.lo += a.lo*b.lo ; d.hi += a.hi*b.hi */
__device__ __forceinline__ void fma2(u64& d, u64 a, u64 b) {
    asm("fma.rn.f32x2 %0, %1, %2, %0;" : "+l"(d) : "l"(a), "l"(b));
}
union F2U { u64 u; float2 f; };
__device__ __forceinline__ float f2sum(u64 v) { F2U t; t.u = v; return t.f.x + t.f.y; }

/* grid-wide barrier: all GRID blocks are co-resident (grid <= #SMs, 1 blk/SM).
 * sense = generation counter; PTX fences are cumulative, so thread0's
 * threadfence after __syncthreads publishes the whole block's writes. */
__device__ __forceinline__ void gridbar() {
    __syncthreads();
    if (threadIdx.x == 0) {
        int gen = g_bar_gen;
        __threadfence();
        if (atomicAdd(&g_bar_count, 1) == GRID - 1) {
            g_bar_count = 0;
            __threadfence();
            g_bar_gen = gen + 1;
        } else {
            while (g_bar_gen == gen) __nanosleep(40);
        }
        __threadfence();
    }
    __syncthreads();
}

/* 4-row GEMM slice: acc[j] += W[row j][k-quarter] . x  (rows rs_u2 u2 apart) */
__device__ __forceinline__ void gemm4(u64* acc, const float* W, int rs_u2,
                                      const float* s_x, int kq, int lane) {
    const ulonglong2* xp = (const ulonglong2*)(s_x + lane * XPAD);
    const ulonglong2* wp = (const ulonglong2*)W;
#pragma unroll 4
    for (int q = kq * 32; q < kq * 32 + 32; q++) {
        ulonglong2 xv = xp[q];
        ulonglong2 w0 = wp[q], w1 = wp[rs_u2 + q], w2 = wp[2 * rs_u2 + q], w3 = wp[3 * rs_u2 + q];
        fma2(acc[0], w0.x, xv.x); fma2(acc[0], w0.y, xv.y);
        fma2(acc[1], w1.x, xv.x); fma2(acc[1], w1.y, xv.y);
        fma2(acc[2], w2.x, xv.x); fma2(acc[2], w2.y, xv.y);
        fma2(acc[3], w3.x, xv.x); fma2(acc[3], w3.y, xv.y);
    }
}

/* ---------------------------------------------------------------------------
 * The whole decode in one persistent kernel. 128 blocks x 512 threads.
 * LSTM: block owns 4 hidden units (16 gate rows). Warp w: gate rq=w>>2,
 * k-quarter kq=w&3. Logits: block owns tiles blk and blk+128 (128 v x 32 b).
 * ------------------------------------------------------------------------- */
__global__ __launch_bounds__(NT) void k_all(
    const float* __restrict__ ctx,  const float* __restrict__ emb,
    const float* __restrict__ Wih0, const float* __restrict__ Whh0,
    const float* __restrict__ bih0, const float* __restrict__ bhh0,
    const float* __restrict__ Wih1, const float* __restrict__ Whh1,
    const float* __restrict__ bih1, const float* __restrict__ bhh1,
    const float* __restrict__ Wout, const float* __restrict__ bout,
    float* __restrict__ out)
{
    extern __shared__ float sm[];
    float* s_x    = sm;                       /* [32][XPAD]  16512 fl */
    float* s_p    = s_x + 32 * XPAD;          /* [4][16][32]  2048 fl */
    float* s_rm   = s_p + 2048;               /* [32][32]     1024 fl */
    float* s_rs   = s_rm + 1024;              /* [32][32]     1024 fl */
    int*   s_ri   = (int*)(s_rs + 1024);      /* [32][32]     1024    */
    int*   s_tok  = s_ri + 1024;              /* [32]                 */
    float* s_fm   = (float*)(s_tok + 32);     /* [32]                 */
    float* s_tile = s_fm + 32;                /* [32][132]    4224 fl */

    int tid = threadIdx.x, blk = blockIdx.x;
    int w = tid >> 5, lane = tid & 31;

    /* ================= pre phase: pre0 + zero states ================= */
    { int i = blk * NT + tid;
      if (i < B * H) { g_h0[0][i] = 0.f; g_h0[1][i] = 0.f; g_c0[i] = 0.f;
                       g_h1[0][i] = 0.f; g_h1[1][i] = 0.f; g_c1[i] = 0.f; } }
    for (int i = tid; i < B * 512; i += NT) {
        int b = i >> 9, k = i & 511;
        s_x[b * XPAD + k] = ctx[i];
    }
    __syncthreads();
    { int r = blk * 16 + w;                   /* 128 blk x 16 warps = 2048 rows */
      const ulonglong2* wp = (const ulonglong2*)(Wih0 + (size_t)r * 1024 + 512);
      const ulonglong2* xp = (const ulonglong2*)(s_x + lane * XPAD);
      u64 a0 = 0, a1 = 0;
#pragma unroll 4
      for (int q = 0; q < 128; q++) {
          ulonglong2 a = wp[q], x = xp[q];
          fma2(a0, a.x, x.x); fma2(a1, a.y, x.y);
      }
      g_pre0[r * 32 + lane] = (f2sum(a0) + f2sum(a1)) + bih0[r] + bhh0[r];
    }
    gridbar();

    /* ================= decode loop ================= */
    for (int t = 0; t <= T; t++) {
        /* ---- prologue: token (all blocks) + lse[t-1] (block 0) ---- */
        if (t > 0) {
            int b = lane, g = w;              /* g 0..15 */
            float m = -3.0e38f; int mi = 0x7fffffff;
            for (int p = g; p < NTILE; p += 16) {
                float pm = g_pmax[p * 32 + b];
                int   pi = g_pidx[p * 32 + b];
                if (pm > m || (pm == m && pi < mi)) { m = pm; mi = pi; }
            }
            s_rm[g * 32 + b] = m; s_ri[g * 32 + b] = mi;
            __syncthreads();
            if (tid < 32) {
                float m2 = s_rm[tid]; int i2 = s_ri[tid];
                for (int g2 = 1; g2 < 16; g2++) {
                    float pm = s_rm[g2 * 32 + tid];
                    int   pi = s_ri[g2 * 32 + tid];
                    if (pm > m2 || (pm == m2 && pi < i2)) { m2 = pm; i2 = pi; }
                }
                s_tok[tid] = i2; s_fm[tid] = m2;
            }
            __syncthreads();
            if (blk == 0) {                   /* lse with independent expfs */
                float mb = s_fm[b];
                float s = 0.0f;
                for (int p = g; p < NTILE; p += 16)
                    s += g_psum[p * 32 + b] * expf(g_pmax[p * 32 + b] - mb);
                s_rs[g * 32 + b] = s;
                __syncthreads();
                if (tid < 32) {
                    float s2 = 0.0f;
                    for (int g2 = 0; g2 < 16; g2++) s2 += s_rs[g2 * 32 + tid];
                    g_lse[(t - 1) * 32 + tid] = s_fm[tid] + logf(s2);
                }
                __syncthreads();
            }
        } else {
            if (tid < 32) s_tok[tid] = START_INDEX;
            __syncthreads();
        }
        if (t == T) break;
        int prev = t & 1, nxt = prev ^ 1;
        int rq = w >> 2, kq = w & 3, j0 = blk * 4;

        /* ---- lstm0 ---- */
        for (int i = tid; i < 32 * 128; i += NT) {
            int b = i >> 7, q = i & 127;
            *(float4*)(s_x + b * XPAD + 4 * q) =
                *(const float4*)(emb + (size_t)s_tok[b] * 512 + 4 * q);
        }
        __syncthreads();
        {
            u64 acc[4] = {0, 0, 0, 0};
            gemm4(acc, Wih0 + (size_t)(rq * 512 + j0) * 1024, 256, s_x, kq, lane);
            __syncthreads();
            for (int i = tid; i < 32 * 128; i += NT) {
                int b = i >> 7, q = i & 127;
                *(float4*)(s_x + b * XPAD + 4 * q) =
                    *(const float4*)(&g_h0[prev][b * 512 + 4 * q]);
            }
            __syncthreads();
            gemm4(acc, Whh0 + (size_t)(rq * 512 + j0) * 512, 128, s_x, kq, lane);
#pragma unroll
            for (int j = 0; j < 4; j++)
                s_p[(kq * 16 + rq * 4 + j) * 32 + lane] = f2sum(acc[j]);
            __syncthreads();
            if (tid < 128) {
                int jl = tid >> 5, b = tid & 31;
                int jg = j0 + jl;
                float gs[4];
#pragma unroll
                for (int g = 0; g < 4; g++) {
                    float s = 0.0f;
#pragma unroll
                    for (int k = 0; k < 4; k++) s += s_p[(k * 16 + g * 4 + jl) * 32 + b];
                    gs[g] = s + g_pre0[(g * 512 + jg) * 32 + b];
                }
                float c  = g_c0[b * 512 + jg];
                float cn = sigf(gs[1]) * c + sigf(gs[0]) * tanhf(gs[2]);
                float hn = sigf(gs[3]) * tanhf(cn);
                g_c0[b * 512 + jg] = cn;
                g_h0[nxt][b * 512 + jg] = hn;
            }
        }
        gridbar();

        /* ---- lstm1 ---- */
        for (int i = tid; i < 32 * 128; i += NT) {
            int b = i >> 7, q = i & 127;
            *(float4*)(s_x + b * XPAD + 4 * q) =
                *(const float4*)(&g_h0[nxt][b * 512 + 4 * q]);
        }
        __syncthreads();
        {
            u64 acc[4] = {0, 0, 0, 0};
            gemm4(acc, Wih1 + (size_t)(rq * 512 + j0) * 512, 128, s_x, kq, lane);
            __syncthreads();
            for (int i = tid; i < 32 * 128; i += NT) {
                int b = i >> 7, q = i & 127;
                *(float4*)(s_x + b * XPAD + 4 * q) =
                    *(const float4*)(&g_h1[prev][b * 512 + 4 * q]);
            }
            __syncthreads();
            gemm4(acc, Whh1 + (size_t)(rq * 512 + j0) * 512, 128, s_x, kq, lane);
#pragma unroll
            for (int j = 0; j < 4; j++)
                s_p[(kq * 16 + rq * 4 + j) * 32 + lane] = f2sum(acc[j]);
            __syncthreads();
            if (tid < 128) {
                int jl = tid >> 5, b = tid & 31;
                int jg = j0 + jl;
                float gs[4];
#pragma unroll
                for (int g = 0; g < 4; g++) {
                    float s = 0.0f;
#pragma unroll
                    for (int k = 0; k < 4; k++) s += s_p[(k * 16 + g * 4 + jl) * 32 + b];
                    int rr = g * 512 + jg;
                    gs[g] = s + bih1[rr] + bhh1[rr];
                }
                float c  = g_c1[b * 512 + jg];
                float cn = sigf(gs[1]) * c + sigf(gs[0]) * tanhf(gs[2]);
                float hn = sigf(gs[3]) * tanhf(cn);
                g_c1[b * 512 + jg] = cn;
                g_h1[nxt][b * 512 + jg] = hn;
            }
        }
        gridbar();

        /* ---- logits: tiles blk and blk+128 (128 v x 32 b each) ---- */
        for (int i = tid; i < 32 * 128; i += NT) {
            int b = i >> 7, q = i & 127;
            *(float4*)(s_x + b * XPAD + 4 * q) =
                *(const float4*)(&g_h1[nxt][b * 512 + 4 * q]);
        }
        __syncthreads();

        for (int it = 0; it < 2; it++) {
            int tile = blk + 128 * it;
            bool act = (tile < NTILE);
            int vb = tile * 128;
            if (act) {
                int vg = tid >> 4, bg = tid & 15;   /* vg 0..31, bg 0..15 */
                u64 a[4][2];
#pragma unroll
                for (int j = 0; j < 4; j++) { a[j][0] = 0; a[j][1] = 0; }
                const ulonglong2* wr = (const ulonglong2*)(Wout + (size_t)(vb + vg) * 512);
#pragma unroll 4
                for (int q = 0; q < 128; q++) {
                    ulonglong2 h0v = *(const ulonglong2*)(s_x + bg * XPAD + 4 * q);
                    ulonglong2 h1v = *(const ulonglong2*)(s_x + (bg + 16) * XPAD + 4 * q);
                    ulonglong2 w0 = wr[q], w1 = wr[4096 + q], w2 = wr[8192 + q], w3 = wr[12288 + q];
                    fma2(a[0][0], w0.x, h0v.x); fma2(a[0][0], w0.y, h0v.y);
                    fma2(a[1][0], w1.x, h0v.x); fma2(a[1][0], w1.y, h0v.y);
                    fma2(a[2][0], w2.x, h0v.x); fma2(a[2][0], w2.y, h0v.y);
                    fma2(a[3][0], w3.x, h0v.x); fma2(a[3][0], w3.y, h0v.y);
                    fma2(a[0][1], w0.x, h1v.x); fma2(a[0][1], w0.y, h1v.y);
                    fma2(a[1][1], w1.x, h1v.x); fma2(a[1][1], w1.y, h1v.y);
                    fma2(a[2][1], w2.x, h1v.x); fma2(a[2][1], w2.y, h1v.y);
                    fma2(a[3][1], w3.x, h1v.x); fma2(a[3][1], w3.y, h1v.y);
                }
                float bj[4];
#pragma unroll
                for (int j = 0; j < 4; j++) bj[j] = bout[vb + vg + 32 * j];
#pragma unroll
                for (int i = 0; i < 2; i++) {
                    int b = bg + 16 * i;
                    float l4[4];
                    float m = -3.0e38f; int mi = 0;
#pragma unroll
                    for (int j = 0; j < 4; j++) {
                        float l = f2sum(a[j][i]) + bj[j];
                        l4[j] = l;
                        int v = vg + 32 * j;
                        if (l > m) { m = l; mi = vb + v; }  /* ascending v: first-index ties */
                        s_tile[b * 132 + v] = l;
                    }
                    float s = 0.f;
#pragma unroll
                    for (int j = 0; j < 4; j++) s += expf(l4[j] - m);
                    s_rm[vg * 32 + b] = m; s_rs[vg * 32 + b] = s; s_ri[vg * 32 + b] = mi;
                }
            }
            __syncthreads();
            if (act) {
                /* coalesced store of the 128x32 tile */
                int b = tid >> 4, vl = (tid & 15) * 8;
                float4 v0 = *(float4*)(s_tile + b * 132 + vl);
                float4 v1 = *(float4*)(s_tile + b * 132 + vl + 4);
                float* dst = &out[(size_t)b * ((size_t)T * V) + (size_t)t * V + vb + vl];
                __stcs((float4*)dst, v0);
                __stcs((float4*)(dst + 4), v1);
                if (tid < 32) {
                    int b2 = tid;
                    float m = s_rm[b2]; int mi = s_ri[b2];
                    for (int g = 1; g < 32; g++) {
                        float pm = s_rm[g * 32 + b2]; int pi = s_ri[g * 32 + b2];
                        if (pm > m || (pm == m && pi < mi)) { m = pm; mi = pi; }
                    }
                    float s = 0.f;
                    for (int g = 0; g < 32; g++)
                        s += s_rs[g * 32 + b2] * expf(s_rm[g * 32 + b2] - m);
                    g_pmax[tile * 32 + b2] = m;
                    g_psum[tile * 32 + b2] = s;
                    g_pidx[tile * 32 + b2] = mi;
                }
            }
            __syncthreads();
        }
        gridbar();
    }

    gridbar();  /* publish g_lse[T-1] before norm */

    /* ================= norm: out -= lse ================= */
    for (int it = 0; it < 250; it++) {
        int i4 = it * (GRID * NT) + blk * NT + tid;   /* < 16,384,000 */
        int flat = i4 * 4;
        int b   = flat / (T * V);
        int rem = flat - b * (T * V);
        int tt  = rem / V;
        float l = g_lse[tt * 32 + b];
        float4* p = (float4*)out + i4;
        float4 v = __ldcs(p);
        v.x -= l; v.y -= l; v.z -= l; v.w -= l;
        __stcs(p, v);
    }
}

/* -------------------------------- launch ---------------------------------- */
#define SMEM_ALL ((32 * XPAD + 2048 + 1024 + 1024 + 1024 + 32 + 32 + 32 * 132) * 4)

extern "C" void kernel_launch(void* const* d_in, const int* in_sizes, int n_in,
                              void* d_out, int out_size) {
    const float* ctx  = (const float*)d_in[0];
    const float* emb  = (const float*)d_in[1];
    const float* Wih0 = (const float*)d_in[2];
    const float* Whh0 = (const float*)d_in[3];
    const float* bih0 = (const float*)d_in[4];
    const float* bhh0 = (const float*)d_in[5];
    const float* Wih1 = (const float*)d_in[6];
    const float* Whh1 = (const float*)d_in[7];
    const float* bih1 = (const float*)d_in[8];
    const float* bhh1 = (const float*)d_in[9];
    const float* Wout = (const float*)d_in[10];
    const float* bout = (const float*)d_in[11];
    float* out = (float*)d_out;

    cudaFuncSetAttribute(k_all, cudaFuncAttributeMaxDynamicSharedMemorySize, SMEM_ALL);
    k_all<<<GRID, NT, SMEM_ALL>>>(ctx, emb, Wih0, Whh0, bih0, bhh0,
                                  Wih1, Whh1, bih1, bhh1, Wout, bout, out);
}

// round 10
// speedup vs baseline: 1.4896x; 1.3040x over previous
#include <cuda_runtime.h>
#include <math.h>
#include <stddef.h>

#define B 32
#define H 512
#define V 32000
#define T 64
#define GRID 128
#define NT 512
#define NTILE 250           /* 250 logits tiles of 128 vocab rows */
#define START_INDEX 1
#define XPAD 516            /* conflict-free 16B smem reads, lane = batch */

typedef unsigned long long u64;

/* ------------------------- persistent device scratch ---------------------- */
__device__ float g_h0[2][B * H];
__device__ float g_c0[B * H];
__device__ float g_h1[2][B * H];
__device__ float g_c1[B * H];
__device__ float g_pre0[2048 * B];  /* ctx part of layer0 gates + b_ih + b_hh */
__device__ float g_pmax[NTILE * B];
__device__ float g_psum[NTILE * B];
__device__ int   g_pidx[NTILE * B];
__device__ float g_lse[T * B];
__device__ int          g_cnt[16];      /* two-level barrier: 16 groups of 8 */
__device__ int          g_cnt_root;
__device__ volatile int g_gen;

__device__ __forceinline__ float sigf(float x) { return 1.0f / (1.0f + expf(-x)); }

/* packed fp32x2 FMA: d.lo += a.lo*b.lo ; d.hi += a.hi*b.hi */
__device__ __forceinline__ void fma2(u64& d, u64 a, u64 b) {
    asm("fma.rn.f32x2 %0, %1, %2, %0;" : "+l"(d) : "l"(a), "l"(b));
}
union F2U { u64 u; float2 f; };
__device__ __forceinline__ float f2sum(u64 v) { F2U t; t.u = v; return t.f.x + t.f.y; }

/* grid barrier, two-level arrivals (8 per leaf counter, 16 roots).
 * Replay-safe: generation captured dynamically (equality test), counters
 * self-reset before the generation flip. All GRID blocks co-resident. */
__device__ __forceinline__ void gridbar() {
    __syncthreads();
    if (threadIdx.x == 0) {
        int gen = g_gen;
        __threadfence();
        if (atomicAdd(&g_cnt[blockIdx.x >> 3], 1) == 7) {
            g_cnt[blockIdx.x >> 3] = 0;
            if (atomicAdd(&g_cnt_root, 1) == 15) {
                g_cnt_root = 0;
                __threadfence();
                g_gen = gen + 1;
            }
        }
        while (g_gen == gen) ;
        __threadfence();
    }
    __syncthreads();
}

/* 4-row GEMM slice: acc[j] += W[row j][k-quarter] . x  (rows rs_u2 u2 apart) */
__device__ __forceinline__ void gemm4(u64* acc, const float* W, int rs_u2,
                                      const float* s_x, int kq, int lane) {
    const ulonglong2* xp = (const ulonglong2*)(s_x + lane * XPAD);
    const ulonglong2* wp = (const ulonglong2*)W;
#pragma unroll 4
    for (int q = kq * 32; q < kq * 32 + 32; q++) {
        ulonglong2 xv = xp[q];
        ulonglong2 w0 = wp[q], w1 = wp[rs_u2 + q], w2 = wp[2 * rs_u2 + q], w3 = wp[3 * rs_u2 + q];
        fma2(acc[0], w0.x, xv.x); fma2(acc[0], w0.y, xv.y);
        fma2(acc[1], w1.x, xv.x); fma2(acc[1], w1.y, xv.y);
        fma2(acc[2], w2.x, xv.x); fma2(acc[2], w2.y, xv.y);
        fma2(acc[3], w3.x, xv.x); fma2(acc[3], w3.y, xv.y);
    }
}

/* combine (m,s,idx) softmax partials; first-index tie rule */
__device__ __forceinline__ void comb(float& m, float& s, int& mi,
                                     float om, float os, int oi) {
    if (om > m || (om == m && oi < mi)) { s = s * expf(m - om) + os; m = om; mi = oi; }
    else                                { s += os * expf(om - m); }
}

/* ---------------------------------------------------------------------------
 * Whole decode in one persistent kernel. 128 blocks x 512 threads.
 * LSTM: block owns 4 hidden units; warp w: gate rq=w>>2, k-quarter kq=w&3.
 * Logits: thread-half owns tile (blk + 128*half), 256 thr, tile 4v x 4b each.
 * Step t also normalizes (subtracts lse) its own tile of step t-1.
 * ------------------------------------------------------------------------- */
__global__ __launch_bounds__(NT) void k_all(
    const float* __restrict__ ctx,  const float* __restrict__ emb,
    const float* __restrict__ Wih0, const float* __restrict__ Whh0,
    const float* __restrict__ bih0, const float* __restrict__ bhh0,
    const float* __restrict__ Wih1, const float* __restrict__ Whh1,
    const float* __restrict__ bih1, const float* __restrict__ bhh1,
    const float* __restrict__ Wout, const float* __restrict__ bout,
    float* __restrict__ out)
{
    extern __shared__ float sm[];
    float* s_x    = sm;                       /* [32][XPAD] 16512 fl (also tile overlay) */
    float* s_p    = s_x + 32 * XPAD;          /* [4][16][32] 2048 fl (LSTM partials) */
    float* s_rm   = s_p + 2048;               /* [16][32] prologue   */
    float* s_rs   = s_rm + 512;
    int*   s_ri   = (int*)(s_rs + 512);
    int*   s_tok  = s_ri + 512;               /* [32] */
    float* s_fm   = (float*)(s_tok + 32);     /* [32] */
    float* s_lse  = s_fm + 32;                /* [32] */
    float* s_Rm   = s_lse + 32;               /* [2][8][8][4] = 512 logits partials */
    float* s_Rs   = s_Rm + 512;
    int*   s_Ri   = (int*)(s_Rs + 512);

    int tid = threadIdx.x, blk = blockIdx.x;
    int w = tid >> 5, lane = tid & 31;

    /* ================= pre phase: pre0 + zero states ================= */
    { int i = blk * NT + tid;
      if (i < B * H) { g_h0[0][i] = 0.f; g_h0[1][i] = 0.f; g_c0[i] = 0.f;
                       g_h1[0][i] = 0.f; g_h1[1][i] = 0.f; g_c1[i] = 0.f; } }
    for (int i = tid; i < B * 512; i += NT) {
        int b = i >> 9, k = i & 511;
        s_x[b * XPAD + k] = ctx[i];
    }
    __syncthreads();
    { int r = blk * 16 + w;                   /* 128 blk x 16 warps = 2048 rows */
      const ulonglong2* wp = (const ulonglong2*)(Wih0 + (size_t)r * 1024 + 512);
      const ulonglong2* xp = (const ulonglong2*)(s_x + lane * XPAD);
      u64 a0 = 0, a1 = 0;
#pragma unroll 4
      for (int q = 0; q < 128; q++) {
          ulonglong2 a = wp[q], x = xp[q];
          fma2(a0, a.x, x.x); fma2(a1, a.y, x.y);
      }
      g_pre0[r * 32 + lane] = (f2sum(a0) + f2sum(a1)) + bih0[r] + bhh0[r];
    }
    gridbar();

    /* ================= decode loop ================= */
    for (int t = 0; t <= T; t++) {
        /* ---- prologue: token (all blocks) + lse[t-1] (block 0) ---- */
        if (t > 0) {
            int b = lane, g = w;              /* g 0..15 */
            float m = -3.0e38f; int mi = 0x7fffffff;
            for (int p = g; p < NTILE; p += 16) {
                float pm = g_pmax[p * 32 + b];
                int   pi = g_pidx[p * 32 + b];
                if (pm > m || (pm == m && pi < mi)) { m = pm; mi = pi; }
            }
            s_rm[g * 32 + b] = m; s_ri[g * 32 + b] = mi;
            __syncthreads();
            if (tid < 32) {
                float m2 = s_rm[tid]; int i2 = s_ri[tid];
                for (int g2 = 1; g2 < 16; g2++) {
                    float pm = s_rm[g2 * 32 + tid];
                    int   pi = s_ri[g2 * 32 + tid];
                    if (pm > m2 || (pm == m2 && pi < i2)) { m2 = pm; i2 = pi; }
                }
                s_tok[tid] = i2; s_fm[tid] = m2;
            }
            __syncthreads();
            if (blk == 0) {                   /* lse with independent expfs */
                float mb = s_fm[b];
                float s = 0.0f;
                for (int p = g; p < NTILE; p += 16)
                    s += g_psum[p * 32 + b] * expf(g_pmax[p * 32 + b] - mb);
                s_rs[g * 32 + b] = s;
                __syncthreads();
                if (tid < 32) {
                    float s2 = 0.0f;
                    for (int g2 = 0; g2 < 16; g2++) s2 += s_rs[g2 * 32 + tid];
                    g_lse[(t - 1) * 32 + tid] = s_fm[tid] + logf(s2);
                }
                __syncthreads();
            }
        } else {
            if (tid < 32) s_tok[tid] = START_INDEX;
            __syncthreads();
        }

        if (t == T) {
            /* final normalization of step T-1 tiles */
            gridbar();                        /* publish g_lse[T-1] */
            if (tid < 32) s_lse[tid] = g_lse[(T - 1) * 32 + tid];
            __syncthreads();
            int half = tid >> 8, th = tid & 255;
            int tile = blk + 128 * half;
            if (tile < NTILE) {
                int b = th >> 3, vl = (th & 7) * 16;
                float lv = s_lse[b];
                float* dst = &out[(size_t)b * ((size_t)T * V) + (size_t)(T - 1) * V
                                  + tile * 128 + vl];
#pragma unroll
                for (int c = 0; c < 4; c++) {
                    float4 vv = *(float4*)(dst + 4 * c);
                    vv.x -= lv; vv.y -= lv; vv.z -= lv; vv.w -= lv;
                    __stcs((float4*)(dst + 4 * c), vv);
                }
            }
            break;
        }

        int prev = t & 1, nxt = prev ^ 1;
        int rq = w >> 2, kq = w & 3, j0 = blk * 4;

        /* ---- lstm0 ---- */
        for (int i = tid; i < 32 * 128; i += NT) {
            int b = i >> 7, q = i & 127;
            *(float4*)(s_x + b * XPAD + 4 * q) =
                *(const float4*)(emb + (size_t)s_tok[b] * 512 + 4 * q);
        }
        __syncthreads();
        {
            u64 acc[4] = {0, 0, 0, 0};
            gemm4(acc, Wih0 + (size_t)(rq * 512 + j0) * 1024, 256, s_x, kq, lane);
            __syncthreads();
            for (int i = tid; i < 32 * 128; i += NT) {
                int b = i >> 7, q = i & 127;
                *(float4*)(s_x + b * XPAD + 4 * q) =
                    *(const float4*)(&g_h0[prev][b * 512 + 4 * q]);
            }
            __syncthreads();
            gemm4(acc, Whh0 + (size_t)(rq * 512 + j0) * 512, 128, s_x, kq, lane);
#pragma unroll
            for (int j = 0; j < 4; j++)
                s_p[(kq * 16 + rq * 4 + j) * 32 + lane] = f2sum(acc[j]);
            __syncthreads();
            if (tid < 128) {
                int jl = tid >> 5, b = tid & 31;
                int jg = j0 + jl;
                float gs[4];
#pragma unroll
                for (int g = 0; g < 4; g++) {
                    float s = 0.0f;
#pragma unroll
                    for (int k = 0; k < 4; k++) s += s_p[(k * 16 + g * 4 + jl) * 32 + b];
                    gs[g] = s + g_pre0[(g * 512 + jg) * 32 + b];
                }
                float c  = g_c0[b * 512 + jg];
                float cn = sigf(gs[1]) * c + sigf(gs[0]) * tanhf(gs[2]);
                float hn = sigf(gs[3]) * tanhf(cn);
                g_c0[b * 512 + jg] = cn;
                g_h0[nxt][b * 512 + jg] = hn;
            }
        }
        gridbar();

        /* ---- lstm1 ---- */
        for (int i = tid; i < 32 * 128; i += NT) {
            int b = i >> 7, q = i & 127;
            *(float4*)(s_x + b * XPAD + 4 * q) =
                *(const float4*)(&g_h0[nxt][b * 512 + 4 * q]);
        }
        __syncthreads();
        {
            u64 acc[4] = {0, 0, 0, 0};
            gemm4(acc, Wih1 + (size_t)(rq * 512 + j0) * 512, 128, s_x, kq, lane);
            __syncthreads();
            for (int i = tid; i < 32 * 128; i += NT) {
                int b = i >> 7, q = i & 127;
                *(float4*)(s_x + b * XPAD + 4 * q) =
                    *(const float4*)(&g_h1[prev][b * 512 + 4 * q]);
            }
            __syncthreads();
            gemm4(acc, Whh1 + (size_t)(rq * 512 + j0) * 512, 128, s_x, kq, lane);
#pragma unroll
            for (int j = 0; j < 4; j++)
                s_p[(kq * 16 + rq * 4 + j) * 32 + lane] = f2sum(acc[j]);
            __syncthreads();
            if (tid < 128) {
                int jl = tid >> 5, b = tid & 31;
                int jg = j0 + jl;
                float gs[4];
#pragma unroll
                for (int g = 0; g < 4; g++) {
                    float s = 0.0f;
#pragma unroll
                    for (int k = 0; k < 4; k++) s += s_p[(k * 16 + g * 4 + jl) * 32 + b];
                    int rr = g * 512 + jg;
                    gs[g] = s + bih1[rr] + bhh1[rr];
                }
                float c  = g_c1[b * 512 + jg];
                float cn = sigf(gs[1]) * c + sigf(gs[0]) * tanhf(gs[2]);
                float hn = sigf(gs[3]) * tanhf(cn);
                g_c1[b * 512 + jg] = cn;
                g_h1[nxt][b * 512 + jg] = hn;
            }
        }
        gridbar();

        /* ---- logits: two tiles (blk, blk+128), 256 threads each ---- */
        for (int i = tid; i < 32 * 128; i += NT) {
            int b = i >> 7, q = i & 127;
            *(float4*)(s_x + b * XPAD + 4 * q) =
                *(const float4*)(&g_h1[nxt][b * 512 + 4 * q]);
        }
        if (t > 0 && tid < 32) s_lse[tid] = g_lse[(t - 1) * 32 + tid];
        __syncthreads();

        int half = tid >> 8, th = tid & 255;
        int tile = blk + 128 * half;
        bool act = (tile < NTILE);
        int vb = tile * 128;
        int vg = th >> 3, bg = th & 7;       /* tile 4v x 4b per thread */
        float l[4][4];                       /* [i][j] kept for the store */

        if (act) {
            const ulonglong2* wp = (const ulonglong2*)(Wout + (size_t)(vb + vg) * 512);
            u64 a[4][4];                     /* [j][i] */
#pragma unroll
            for (int j = 0; j < 4; j++)
#pragma unroll
                for (int i = 0; i < 4; i++) a[j][i] = 0;

            ulonglong2 wb[4];
#pragma unroll
            for (int j = 0; j < 4; j++) wb[j] = wp[j * 4096];

#pragma unroll 2
            for (int q = 0; q < 127; q++) {
                ulonglong2 wc[4];
#pragma unroll
                for (int j = 0; j < 4; j++) wc[j] = wb[j];
#pragma unroll
                for (int j = 0; j < 4; j++) wb[j] = wp[j * 4096 + q + 1];
                ulonglong2 hv[4];
#pragma unroll
                for (int i = 0; i < 4; i++)
                    hv[i] = *(const ulonglong2*)(s_x + (bg + 8 * i) * XPAD + 4 * q);
#pragma unroll
                for (int j = 0; j < 4; j++)
#pragma unroll
                    for (int i = 0; i < 4; i++) {
                        fma2(a[j][i], wc[j].x, hv[i].x);
                        fma2(a[j][i], wc[j].y, hv[i].y);
                    }
            }
            {   /* q = 127 */
                ulonglong2 hv[4];
#pragma unroll
                for (int i = 0; i < 4; i++)
                    hv[i] = *(const ulonglong2*)(s_x + (bg + 8 * i) * XPAD + 4 * 127);
#pragma unroll
                for (int j = 0; j < 4; j++)
#pragma unroll
                    for (int i = 0; i < 4; i++) {
                        fma2(a[j][i], wb[j].x, hv[i].x);
                        fma2(a[j][i], wb[j].y, hv[i].y);
                    }
            }

            float bj[4];
#pragma unroll
            for (int j = 0; j < 4; j++) bj[j] = bout[vb + vg + 32 * j];

            int lw = th & 31;                /* lane within warp */
#pragma unroll
            for (int i = 0; i < 4; i++) {
                float m = -3.0e38f; int mi = 0;
#pragma unroll
                for (int j = 0; j < 4; j++) {
                    float lv = f2sum(a[j][i]) + bj[j];
                    l[i][j] = lv;
                    if (lv > m) { m = lv; mi = vb + vg + 32 * j; }
                }
                float s = 0.f;
#pragma unroll
                for (int j = 0; j < 4; j++) s += expf(l[i][j] - m);
                /* reduce over the 4 vg values in this warp (lane bits 3,4) */
#pragma unroll
                for (int off = 8; off <= 16; off <<= 1) {
                    float om = __shfl_xor_sync(0xffffffffu, m, off);
                    float os = __shfl_xor_sync(0xffffffffu, s, off);
                    int   oi = __shfl_xor_sync(0xffffffffu, mi, off);
                    comb(m, s, mi, om, os, oi);
                }
                if (lw < 8) {
                    int idx = half * 256 + (th >> 5) * 32 + bg * 4 + i;
                    s_Rm[idx] = m; s_Rs[idx] = s; s_Ri[idx] = mi;
                }
            }
        }
        __syncthreads();                     /* fma done: s_x free for overlay */

        /* stage tile into smem overlay for coalesced stores */
        float* s_ov = s_x + half * 4224;     /* [32][132] per half */
        if (act) {
#pragma unroll
            for (int i = 0; i < 4; i++)
#pragma unroll
                for (int j = 0; j < 4; j++)
                    s_ov[(bg + 8 * i) * 132 + vg + 32 * j] = l[i][j];
        }
        /* final per-tile softmax partials (8 warps -> 1) */
        if (tid < 64) {
            int tl = tid >> 5, b = tid & 31;
            int t2 = blk + 128 * tl;
            if (t2 < NTILE) {
                int bg2 = b & 7, i2 = b >> 3;
                float m = -3.0e38f, s = 0.f; int mi = 0x7fffffff;
                for (int w2 = 0; w2 < 8; w2++) {
                    int idx = tl * 256 + w2 * 32 + bg2 * 4 + i2;
                    comb(m, s, mi, s_Rm[idx], s_Rs[idx], s_Ri[idx]);
                }
                g_pmax[t2 * 32 + b] = m;
                g_psum[t2 * 32 + b] = s;
                g_pidx[t2 * 32 + b] = mi;
            }
        }
        __syncthreads();

        if (act) {
            /* coalesced raw-logit store */
            int b = th >> 3, vl = (th & 7) * 16;
            const float* src = s_ov + b * 132 + vl;
            float* dst = &out[(size_t)b * ((size_t)T * V) + (size_t)t * V + vb + vl];
#pragma unroll
            for (int c = 0; c < 4; c++)
                __stcs((float4*)(dst + 4 * c), *(const float4*)(src + 4 * c));
            /* normalize own tile of step t-1 (lse[t-1] known since prologue) */
            if (t > 0) {
                float lv = s_lse[b];
                float* pd = &out[(size_t)b * ((size_t)T * V) + (size_t)(t - 1) * V + vb + vl];
#pragma unroll
                for (int c = 0; c < 4; c++) {
                    float4 vv = *(float4*)(pd + 4 * c);
                    vv.x -= lv; vv.y -= lv; vv.z -= lv; vv.w -= lv;
                    __stcs((float4*)(pd + 4 * c), vv);
                }
            }
        }
        gridbar();
    }
}

/* -------------------------------- launch ---------------------------------- */
#define SMEM_ALL ((32 * XPAD + 2048 + 512 * 3 + 32 * 3 + 512 * 3) * 4)

extern "C" void kernel_launch(void* const* d_in, const int* in_sizes, int n_in,
                              void* d_out, int out_size) {
    const float* ctx  = (const float*)d_in[0];
    const float* emb  = (const float*)d_in[1];
    const float* Wih0 = (const float*)d_in[2];
    const float* Whh0 = (const float*)d_in[3];
    const float* bih0 = (const float*)d_in[4];
    const float* bhh0 = (const float*)d_in[5];
    const float* Wih1 = (const float*)d_in[6];
    const float* Whh1 = (const float*)d_in[7];
    const float* bih1 = (const float*)d_in[8];
    const float* bhh1 = (const float*)d_in[9];
    const float* Wout = (const float*)d_in[10];
    const float* bout = (const float*)d_in[11];
    float* out = (float*)d_out;

    cudaFuncSetAttribute(k_all, cudaFuncAttributeMaxDynamicSharedMemorySize, SMEM_ALL);
    k_all<<<GRID, NT, SMEM_ALL>>>(ctx, emb, Wih0, Whh0, bih0, bhh0,
                                  Wih1, Whh1, bih1, bhh1, Wout, bout, out);
}

// round 11
// speedup vs baseline: 1.5174x; 1.0186x over previous
#include <cuda_runtime.h>
#include <stdio.h>
#include <math.h>
#include <stddef.h>

#define B 32
#define H 512
#define V 32000
#define T 64
#define GRID 128
#define NT 512
#define NTILE 250           /* 250 logits tiles of 128 vocab rows */
#define START_INDEX 1
#define XPAD 516            /* conflict-free 16B smem reads, lane = batch */

typedef unsigned long long u64;

/* ------------------------- persistent device scratch ---------------------- */
__device__ float g_h0[2][B * H];
__device__ float g_c0[B * H];
__device__ float g_h1[2][B * H];
__device__ float g_c1[B * H];
__device__ float g_pre0[2048 * B];  /* ctx part of layer0 gates + b_ih + b_hh */
__device__ float g_pmax[NTILE * B];
__device__ float g_psum[NTILE * B];
__device__ u64   g_amax[2][B];      /* packed (sortable(max)<<32)|~idx, per parity */
__device__ float g_lsp[8][B];       /* distributed deterministic LSE partials */
__device__ int          g_cnt[16];  /* two-level barrier */
__device__ int          g_cnt_root;
__device__ volatile int g_gen;

__device__ __forceinline__ float sigf(float x) { return 1.0f / (1.0f + expf(-x)); }

/* packed fp32x2 FMA: d.lo += a.lo*b.lo ; d.hi += a.hi*b.hi */
__device__ __forceinline__ void fma2(u64& d, u64 a, u64 b) {
    asm("fma.rn.f32x2 %0, %1, %2, %0;" : "+l"(d) : "l"(a), "l"(b));
}
union F2U { u64 u; float2 f; };
__device__ __forceinline__ float f2sum(u64 v) { F2U t; t.u = v; return t.f.x + t.f.y; }

/* order-preserving float<->u32 ("sortable") transform */
__device__ __forceinline__ unsigned fsort(float x) {
    unsigned u = __float_as_uint(x);
    return u ^ ((unsigned)(((int)u) >> 31) | 0x80000000u);
}
__device__ __forceinline__ float funsort(unsigned s) {
    unsigned u = (s & 0x80000000u) ? (s ^ 0x80000000u) : ~s;
    return __uint_as_float(u);
}
__device__ __forceinline__ u64 packkey(float m, int idx) {
    return ((u64)fsort(m) << 32) | (u64)(~(unsigned)idx);
}

/* grid barrier, two-level arrivals; replay-safe; all GRID blocks co-resident */
__device__ __forceinline__ void gridbar() {
    __syncthreads();
    if (threadIdx.x == 0) {
        int gen = g_gen;
        __threadfence();
        if (atomicAdd(&g_cnt[blockIdx.x >> 3], 1) == 7) {
            g_cnt[blockIdx.x >> 3] = 0;
            if (atomicAdd(&g_cnt_root, 1) == 15) {
                g_cnt_root = 0;
                __threadfence();
                g_gen = gen + 1;
            }
        }
        while (g_gen == gen) __nanosleep(32);
        __threadfence();
    }
    __syncthreads();
}

/* 4-row GEMM slice: acc[j] += W[row j][k-quarter] . x  (rows rs_u2 u2 apart) */
__device__ __forceinline__ void gemm4(u64* acc, const float* W, int rs_u2,
                                      const float* s_x, int kq, int lane) {
    const ulonglong2* xp = (const ulonglong2*)(s_x + lane * XPAD);
    const ulonglong2* wp = (const ulonglong2*)W;
#pragma unroll 4
    for (int q = kq * 32; q < kq * 32 + 32; q++) {
        ulonglong2 xv = xp[q];
        ulonglong2 w0 = wp[q], w1 = wp[rs_u2 + q], w2 = wp[2 * rs_u2 + q], w3 = wp[3 * rs_u2 + q];
        fma2(acc[0], w0.x, xv.x); fma2(acc[0], w0.y, xv.y);
        fma2(acc[1], w1.x, xv.x); fma2(acc[1], w1.y, xv.y);
        fma2(acc[2], w2.x, xv.x); fma2(acc[2], w2.y, xv.y);
        fma2(acc[3], w3.x, xv.x); fma2(acc[3], w3.y, xv.y);
    }
}

/* combine (m,s,idx) softmax partials; first-index tie rule */
__device__ __forceinline__ void comb(float& m, float& s, int& mi,
                                     float om, float os, int oi) {
    if (om > m || (om == m && oi < mi)) { s = s * expf(m - om) + os; m = om; mi = oi; }
    else                                { s += os * expf(om - m); }
}

#define TICK(var) do { if (blk == 0 && tid == 0) { long long c1 = clock64(); var += c1 - tc0; tc0 = c1; } } while (0)

/* ---------------------------------------------------------------------------
 * Whole decode, one persistent kernel. 128 blocks x 512 threads.
 * ------------------------------------------------------------------------- */
__global__ __launch_bounds__(NT) void k_all(
    const float* __restrict__ ctx,  const float* __restrict__ emb,
    const float* __restrict__ Wih0, const float* __restrict__ Whh0,
    const float* __restrict__ bih0, const float* __restrict__ bhh0,
    const float* __restrict__ Wih1, const float* __restrict__ Whh1,
    const float* __restrict__ bih1, const float* __restrict__ bhh1,
    const float* __restrict__ Wout, const float* __restrict__ bout,
    float* __restrict__ out)
{
    extern __shared__ float sm[];
    float* s_x    = sm;                       /* [32][XPAD] 16512 fl (also store overlay) */
    float* s_p    = s_x + 32 * XPAD;          /* [4][16][32] LSTM partials */
    float* s_rs   = s_p + 2048;               /* [16][32] LSE partial reduce */
    int*   s_tok  = (int*)(s_rs + 512);       /* [32] */
    float* s_fm   = (float*)(s_tok + 32);     /* [32] */
    float* s_lse  = s_fm + 32;                /* [32] */
    float* s_Rm   = s_lse + 32;               /* [512] logits warp partials */
    float* s_Rs   = s_Rm + 512;
    int*   s_Ri   = (int*)(s_Rs + 512);

    int tid = threadIdx.x, blk = blockIdx.x;
    int w = tid >> 5, lane = tid & 31;

    long long tc0 = 0, a_pro = 0, a_l0 = 0, a_b1 = 0, a_l1 = 0, a_b2 = 0, a_lg = 0, a_b3 = 0;

    /* ================= pre phase ================= */
    { int i = blk * NT + tid;
      if (i < B * H) { g_h0[0][i] = 0.f; g_h0[1][i] = 0.f; g_c0[i] = 0.f;
                       g_h1[0][i] = 0.f; g_h1[1][i] = 0.f; g_c1[i] = 0.f; } }
    if (blk == 0 && tid < 64) ((u64*)g_amax)[tid] = 0ull;   /* key 0 < any real key */
    for (int i = tid; i < B * 512; i += NT) {
        int b = i >> 9, k = i & 511;
        s_x[b * XPAD + k] = ctx[i];
    }
    __syncthreads();
    { int r = blk * 16 + w;
      const ulonglong2* wp = (const ulonglong2*)(Wih0 + (size_t)r * 1024 + 512);
      const ulonglong2* xp = (const ulonglong2*)(s_x + lane * XPAD);
      u64 a0 = 0, a1 = 0;
#pragma unroll 4
      for (int q = 0; q < 128; q++) {
          ulonglong2 a = wp[q], x = xp[q];
          fma2(a0, a.x, x.x); fma2(a1, a.y, x.y);
      }
      g_pre0[r * 32 + lane] = (f2sum(a0) + f2sum(a1)) + bih0[r] + bhh0[r];
    }
    gridbar();

    /* ================= decode loop ================= */
    for (int t = 0; t <= T; t++) {
        if (blk == 0 && tid == 0) tc0 = clock64();
        /* ---- prologue ---- */
        if (t > 0) {
            if (tid < 32) {
                u64 key = g_amax[(t - 1) & 1][tid];
                s_tok[tid] = (int)(~(unsigned)(key & 0xffffffffu));
                s_fm[tid]  = funsort((unsigned)(key >> 32));
            }
            __syncthreads();
            if (blk < 8) {      /* deterministic distributed LSE partials */
                int b = lane, g = w;
                float mb = s_fm[b];
                float s = 0.0f;
#pragma unroll
                for (int k = 0; k < 2; k++) {
                    int p = blk * 32 + g + 16 * k;
                    if (p < NTILE)
                        s += g_psum[p * 32 + b] * expf(g_pmax[p * 32 + b] - mb);
                }
                s_rs[g * 32 + b] = s;
                __syncthreads();
                if (tid < 32) {
                    float s2 = 0.0f;
                    for (int g2 = 0; g2 < 16; g2++) s2 += s_rs[g2 * 32 + tid];
                    g_lsp[blk][tid] = s2;
                }
            }
        } else {
            if (tid < 32) s_tok[tid] = START_INDEX;
            __syncthreads();
        }
        TICK(a_pro);

        if (t == T) {
            gridbar();          /* publish g_lsp for T-1 */
            if (tid < 32) {
                float s2 = 0.0f;
#pragma unroll
                for (int k = 0; k < 8; k++) s2 += g_lsp[k][tid];
                s_lse[tid] = s_fm[tid] + logf(s2);
            }
            __syncthreads();
            int half = tid >> 8, th = tid & 255;
            int tile = blk + 128 * half;
            if (tile < NTILE) {
                int b = th >> 3, vl = (th & 7) * 16;
                float lv = s_lse[b];
                float* dst = &out[(size_t)b * ((size_t)T * V) + (size_t)(T - 1) * V
                                  + tile * 128 + vl];
#pragma unroll
                for (int c = 0; c < 4; c++) {
                    float4 vv = *(float4*)(dst + 4 * c);
                    vv.x -= lv; vv.y -= lv; vv.z -= lv; vv.w -= lv;
                    __stcs((float4*)(dst + 4 * c), vv);
                }
            }
            break;
        }

        int prev = t & 1, nxt = prev ^ 1;
        int rq = w >> 2, kq = w & 3, j0 = blk * 4;

        /* ---- lstm0 ---- */
        for (int i = tid; i < 32 * 128; i += NT) {
            int b = i >> 7, q = i & 127;
            *(float4*)(s_x + b * XPAD + 4 * q) =
                *(const float4*)(emb + (size_t)s_tok[b] * 512 + 4 * q);
        }
        __syncthreads();
        {
            u64 acc[4] = {0, 0, 0, 0};
            gemm4(acc, Wih0 + (size_t)(rq * 512 + j0) * 1024, 256, s_x, kq, lane);
            __syncthreads();
            for (int i = tid; i < 32 * 128; i += NT) {
                int b = i >> 7, q = i & 127;
                *(float4*)(s_x + b * XPAD + 4 * q) =
                    *(const float4*)(&g_h0[prev][b * 512 + 4 * q]);
            }
            __syncthreads();
            gemm4(acc, Whh0 + (size_t)(rq * 512 + j0) * 512, 128, s_x, kq, lane);
#pragma unroll
            for (int j = 0; j < 4; j++)
                s_p[(kq * 16 + rq * 4 + j) * 32 + lane] = f2sum(acc[j]);
            __syncthreads();
            if (tid < 128) {
                int jl = tid >> 5, b = tid & 31;
                int jg = j0 + jl;
                float gs[4];
#pragma unroll
                for (int g = 0; g < 4; g++) {
                    float s = 0.0f;
#pragma unroll
                    for (int k = 0; k < 4; k++) s += s_p[(k * 16 + g * 4 + jl) * 32 + b];
                    gs[g] = s + g_pre0[(g * 512 + jg) * 32 + b];
                }
                float c  = g_c0[b * 512 + jg];
                float cn = sigf(gs[1]) * c + sigf(gs[0]) * tanhf(gs[2]);
                float hn = sigf(gs[3]) * tanhf(cn);
                g_c0[b * 512 + jg] = cn;
                g_h0[nxt][b * 512 + jg] = hn;
            }
        }
        TICK(a_l0);
        gridbar();
        TICK(a_b1);

        /* reset amax parity used this prologue (next written at logits t+1) */
        if (blk == 0 && tid < 32) g_amax[(t - 1) & 1][tid] = 0ull;

        /* ---- lstm1 ---- */
        for (int i = tid; i < 32 * 128; i += NT) {
            int b = i >> 7, q = i & 127;
            *(float4*)(s_x + b * XPAD + 4 * q) =
                *(const float4*)(&g_h0[nxt][b * 512 + 4 * q]);
        }
        __syncthreads();
        {
            u64 acc[4] = {0, 0, 0, 0};
            gemm4(acc, Wih1 + (size_t)(rq * 512 + j0) * 512, 128, s_x, kq, lane);
            __syncthreads();
            for (int i = tid; i < 32 * 128; i += NT) {
                int b = i >> 7, q = i & 127;
                *(float4*)(s_x + b * XPAD + 4 * q) =
                    *(const float4*)(&g_h1[prev][b * 512 + 4 * q]);
            }
            __syncthreads();
            gemm4(acc, Whh1 + (size_t)(rq * 512 + j0) * 512, 128, s_x, kq, lane);
#pragma unroll
            for (int j = 0; j < 4; j++)
                s_p[(kq * 16 + rq * 4 + j) * 32 + lane] = f2sum(acc[j]);
            __syncthreads();
            if (tid < 128) {
                int jl = tid >> 5, b = tid & 31;
                int jg = j0 + jl;
                float gs[4];
#pragma unroll
                for (int g = 0; g < 4; g++) {
                    float s = 0.0f;
#pragma unroll
                    for (int k = 0; k < 4; k++) s += s_p[(k * 16 + g * 4 + jl) * 32 + b];
                    int rr = g * 512 + jg;
                    gs[g] = s + bih1[rr] + bhh1[rr];
                }
                float c  = g_c1[b * 512 + jg];
                float cn = sigf(gs[1]) * c + sigf(gs[0]) * tanhf(gs[2]);
                float hn = sigf(gs[3]) * tanhf(cn);
                g_c1[b * 512 + jg] = cn;
                g_h1[nxt][b * 512 + jg] = hn;
            }
        }
        TICK(a_l1);
        gridbar();
        TICK(a_b2);

        /* ---- logits ---- */
        for (int i = tid; i < 32 * 128; i += NT) {
            int b = i >> 7, q = i & 127;
            *(float4*)(s_x + b * XPAD + 4 * q) =
                *(const float4*)(&g_h1[nxt][b * 512 + 4 * q]);
        }
        if (t > 0 && tid < 32) {
            float s2 = 0.0f;
#pragma unroll
            for (int k = 0; k < 8; k++) s2 += g_lsp[k][tid];
            s_lse[tid] = s_fm[tid] + logf(s2);
        }
        __syncthreads();

        int half = tid >> 8, th = tid & 255;
        int tile = blk + 128 * half;
        bool act = (tile < NTILE);
        int vb = tile * 128;
        int vg = th >> 3, bg = th & 7;       /* thread tile 4v x 4b */
        float l[4][4];

        if (act) {
            const ulonglong2* wp = (const ulonglong2*)(Wout + (size_t)(vb + vg) * 512);
            u64 a[4][4];
#pragma unroll
            for (int j = 0; j < 4; j++)
#pragma unroll
                for (int i = 0; i < 4; i++) a[j][i] = 0;

            /* 2-deep ping-pong weight prefetch */
            ulonglong2 wA[4], wB[4];
#pragma unroll
            for (int j = 0; j < 4; j++) wA[j] = wp[j * 4096 + 0];
#pragma unroll
            for (int j = 0; j < 4; j++) wB[j] = wp[j * 4096 + 1];

            for (int q = 0; q < 128; q += 2) {
                int qa = (q + 2 < 128) ? (q + 2) : 126;
                int qb = (q + 3 < 128) ? (q + 3) : 127;
                {
                    ulonglong2 hv[4];
#pragma unroll
                    for (int i = 0; i < 4; i++)
                        hv[i] = *(const ulonglong2*)(s_x + (bg + 8 * i) * XPAD + 4 * q);
#pragma unroll
                    for (int j = 0; j < 4; j++)
#pragma unroll
                        for (int i = 0; i < 4; i++) {
                            fma2(a[j][i], wA[j].x, hv[i].x);
                            fma2(a[j][i], wA[j].y, hv[i].y);
                        }
#pragma unroll
                    for (int j = 0; j < 4; j++) wA[j] = wp[j * 4096 + qa];
                }
                {
                    ulonglong2 hv[4];
#pragma unroll
                    for (int i = 0; i < 4; i++)
                        hv[i] = *(const ulonglong2*)(s_x + (bg + 8 * i) * XPAD + 4 * (q + 1));
#pragma unroll
                    for (int j = 0; j < 4; j++)
#pragma unroll
                        for (int i = 0; i < 4; i++) {
                            fma2(a[j][i], wB[j].x, hv[i].x);
                            fma2(a[j][i], wB[j].y, hv[i].y);
                        }
#pragma unroll
                    for (int j = 0; j < 4; j++) wB[j] = wp[j * 4096 + qb];
                }
            }

            float bj[4];
#pragma unroll
            for (int j = 0; j < 4; j++) bj[j] = bout[vb + vg + 32 * j];

            int lw = th & 31;
#pragma unroll
            for (int i = 0; i < 4; i++) {
                float m = -3.0e38f; int mi = 0;
#pragma unroll
                for (int j = 0; j < 4; j++) {
                    float lv = f2sum(a[j][i]) + bj[j];
                    l[i][j] = lv;
                    if (lv > m) { m = lv; mi = vb + vg + 32 * j; }
                }
                float s = 0.f;
#pragma unroll
                for (int j = 0; j < 4; j++) s += expf(l[i][j] - m);
#pragma unroll
                for (int off = 8; off <= 16; off <<= 1) {
                    float om = __shfl_xor_sync(0xffffffffu, m, off);
                    float os = __shfl_xor_sync(0xffffffffu, s, off);
                    int   oi = __shfl_xor_sync(0xffffffffu, mi, off);
                    comb(m, s, mi, om, os, oi);
                }
                if (lw < 8) {
                    int idx = half * 256 + (th >> 5) * 32 + bg * 4 + i;
                    s_Rm[idx] = m; s_Rs[idx] = s; s_Ri[idx] = mi;
                }
            }
        }
        __syncthreads();                     /* s_x free for overlay */

        float* s_ov = s_x + half * 4224;     /* [32][132] per half */
        if (act) {
#pragma unroll
            for (int i = 0; i < 4; i++)
#pragma unroll
                for (int j = 0; j < 4; j++)
                    s_ov[(bg + 8 * i) * 132 + vg + 32 * j] = l[i][j];
        }
        if (tid < 64) {                      /* per-tile combine + global argmax */
            int tl = tid >> 5, b = tid & 31;
            int t2 = blk + 128 * tl;
            if (t2 < NTILE) {
                int bg2 = b & 7, i2 = b >> 3;
                float m = -3.0e38f, s = 0.f; int mi = 0x7fffffff;
                for (int w2 = 0; w2 < 8; w2++) {
                    int idx = tl * 256 + w2 * 32 + bg2 * 4 + i2;
                    comb(m, s, mi, s_Rm[idx], s_Rs[idx], s_Ri[idx]);
                }
                g_pmax[t2 * 32 + b] = m;
                g_psum[t2 * 32 + b] = s;
                atomicMax(&g_amax[t & 1][b], packkey(m, mi));
            }
        }
        __syncthreads();

        if (act) {
            int b = th >> 3, vl = (th & 7) * 16;
            const float* src = s_ov + b * 132 + vl;
            float* dst = &out[(size_t)b * ((size_t)T * V) + (size_t)t * V + vb + vl];
#pragma unroll
            for (int c = 0; c < 4; c++)
                __stcs((float4*)(dst + 4 * c), *(const float4*)(src + 4 * c));
            if (t > 0) {                     /* normalize own tile of step t-1 */
                float lv = s_lse[b];
                float* pd = &out[(size_t)b * ((size_t)T * V) + (size_t)(t - 1) * V + vb + vl];
#pragma unroll
                for (int c = 0; c < 4; c++) {
                    float4 vv = *(float4*)(pd + 4 * c);
                    vv.x -= lv; vv.y -= lv; vv.z -= lv; vv.w -= lv;
                    __stcs((float4*)(pd + 4 * c), vv);
                }
            }
        }
        TICK(a_lg);
        gridbar();
        TICK(a_b3);
    }

    if (blk == 0 && tid == 0)
        printf("PHASECYC pro=%lld l0=%lld b1=%lld l1=%lld b2=%lld lg=%lld b3=%lld\n",
               a_pro, a_l0, a_b1, a_l1, a_b2, a_lg, a_b3);
}

/* -------------------------------- launch ---------------------------------- */
#define SMEM_ALL ((32 * XPAD + 2048 + 512 + 32 * 3 + 512 * 3) * 4)

extern "C" void kernel_launch(void* const* d_in, const int* in_sizes, int n_in,
                              void* d_out, int out_size) {
    const float* ctx  = (const float*)d_in[0];
    const float* emb  = (const float*)d_in[1];
    const float* Wih0 = (const float*)d_in[2];
    const float* Whh0 = (const float*)d_in[3];
    const float* bih0 = (const float*)d_in[4];
    const float* bhh0 = (const float*)d_in[5];
    const float* Wih1 = (const float*)d_in[6];
    const float* Whh1 = (const float*)d_in[7];
    const float* bih1 = (const float*)d_in[8];
    const float* bhh1 = (const float*)d_in[9];
    const float* Wout = (const float*)d_in[10];
    const float* bout = (const float*)d_in[11];
    float* out = (float*)d_out;

    cudaFuncSetAttribute(k_all, cudaFuncAttributeMaxDynamicSharedMemorySize, SMEM_ALL);
    k_all<<<GRID, NT, SMEM_ALL>>>(ctx, emb, Wih0, Whh0, bih0, bhh0,
                                  Wih1, Whh1, bih1, bhh1, Wout, bout, out);
}